// round 14
// baseline (speedup 1.0000x reference)
#include <cuda_runtime.h>

#define NN 8192
#define D 64
#define ALPHA 0.2f
#define CS 32          // scan chunk size (one warp-scan, no carry chain)
#define NC 256         // number of chunks (NN/CS)
#define HTS 33         // half-tile stride: 33 % 32 == 1 -> conflict-free columns

// ---------------- device scratch (no allocation allowed) ----------------
__device__ float g_h[NN * D];
__device__ float g_hs[NN * D];         // h rows in SORTED order (gather done in kRank)
__device__ float g_f1[NN];
__device__ float g_f2[NN];
__device__ unsigned g_key[NN];
__device__ unsigned g_rank[NN];        // low 20 bits: rank accum; bits 20+: arrival count
__device__ float g_f2s[NN];
__device__ float g_wlo[NN];            // exp(alpha * f2), sorted order
__device__ float g_whi[NN];            // exp(f2), sorted order
__device__ float g_LoP[(NN + 1) * D];  // chunk-local fwd prefix of wlo*h
__device__ float g_HiS[(NN + 1) * D];  // chunk-local bwd suffix of whi*h
__device__ float g_zLo[NN + 1];
__device__ float g_zHi[NN + 1];
__device__ float g_ofLo[D * NC];       // [d][c] totals -> exclusive offsets (in place)
__device__ float g_ofHi[D * NC];       // [d][c]
__device__ float g_ofzLo[NC];
__device__ float g_ofzHi[NC];

// ---------------- k1: h = x@Wt (16 rows/block), f1/f2, 32-bit keys, zero ranks ----------------
__global__ void k1(const float* __restrict__ x, const float* __restrict__ Wt,
                   const float* __restrict__ a1, const float* __restrict__ b1,
                   const float* __restrict__ a2, const float* __restrict__ b2) {
    __shared__ float sW[D * D];
    __shared__ float sx[16][D];
    __shared__ float sh[16][D];
    int tid = threadIdx.x;        // 256
    int row0 = blockIdx.x * 16;
    for (int i = tid; i < D * D; i += 256) sW[i] = Wt[i];
    for (int i = tid; i < 16 * D; i += 256) sx[i >> 6][i & 63] = x[row0 * D + i];
    __syncthreads();
    int o = tid & 63, rg = tid >> 6;
    float a0 = 0.f, a1c = 0.f, a2c = 0.f, a3 = 0.f;
#pragma unroll
    for (int i = 0; i < D; i++) {
        float w = sW[i * D + o];
        a0  += sx[rg * 4 + 0][i] * w;
        a1c += sx[rg * 4 + 1][i] * w;
        a2c += sx[rg * 4 + 2][i] * w;
        a3  += sx[rg * 4 + 3][i] * w;
    }
    g_h[(row0 + rg * 4 + 0) * D + o] = a0;
    g_h[(row0 + rg * 4 + 1) * D + o] = a1c;
    g_h[(row0 + rg * 4 + 2) * D + o] = a2c;
    g_h[(row0 + rg * 4 + 3) * D + o] = a3;
    sh[rg * 4 + 0][o] = a0;
    sh[rg * 4 + 1][o] = a1c;
    sh[rg * 4 + 2][o] = a2c;
    sh[rg * 4 + 3][o] = a3;
    __syncthreads();
    int w = tid >> 5, lane = tid & 31;
#pragma unroll
    for (int q = 0; q < 2; q++) {
        int r = w * 2 + q;
        float h0 = sh[r][lane], h1 = sh[r][lane + 32];
        float s1 = h0 * a1[lane] + h1 * a1[lane + 32];
        float s2 = h0 * a2[lane] + h1 * a2[lane + 32];
#pragma unroll
        for (int off = 16; off; off >>= 1) {
            s1 += __shfl_down_sync(0xFFFFFFFFu, s1, off);
            s2 += __shfl_down_sync(0xFFFFFFFFu, s2, off);
        }
        if (lane == 0) {
            int row = row0 + r;
            float f1v = s1 + b1[0], f2v = s2 + b2[0];
            g_f1[row] = f1v;
            g_f2[row] = f2v;
            unsigned u = __float_as_uint(f2v);
            g_key[row] = (u >> 31) ? ~u : (u | 0x80000000u);  // order-preserving
            g_rank[row] = 0u;
        }
    }
}

// ---------------- kRank: brute-force counting rank + FUSED scatter (incl. h row) ----------------
// 1024 blocks = eb(64, element-chunk of 128) x cb(16, key-chunk of 512).
// Region tie-break: blocks below diagonal use <=, above use <, diagonal exact.
__global__ void kRank() {
    __shared__ unsigned sk[512];
    int tid = threadIdx.x;  // 128
    int eb = blockIdx.x >> 4, cb = blockIdx.x & 15;
    int i = eb * 128 + tid;
    unsigned ki = g_key[i];
#pragma unroll
    for (int m = 0; m < 4; m++) sk[tid + m * 128] = g_key[cb * 512 + tid + m * 128];
    __syncthreads();
    unsigned cnt = 0;
    int diag = eb >> 2;    // cb containing this eb's i-range
    if (cb == diag) {
        int j0 = cb * 512;
        for (int j = 0; j < 512; j++) {
            unsigned kj = sk[j];
            cnt += (kj < ki) || (kj == ki && (j0 + j) < i);
        }
    } else if (cb < diag) {   // all j < i: ties count
#pragma unroll 8
        for (int j = 0; j < 512; j++) cnt += (sk[j] <= ki);
    } else {                  // all j > i: ties don't count
#pragma unroll 8
        for (int j = 0; j < 512; j++) cnt += (sk[j] < ki);
    }
    unsigned old = atomicAdd(&g_rank[i], cnt + (1u << 20));
    if ((old >> 20) == 15u) {                 // final arrival performs scatter
        int r = (int)((old & 0xFFFFFu) + cnt);
        float f = g_f2[i];
        g_f2s[r] = f;
        g_wlo[r] = expf(ALPHA * f);
        g_whi[r] = expf(f);
        // copy the h row into sorted position (removes gather indirection in kScan)
        float4* dst = (float4*)(g_hs + (size_t)r * D);
        const float4* src = (const float4*)(g_h + (size_t)i * D);
#pragma unroll
        for (int m = 0; m < 16; m++) dst[m] = src[m];
    }
}

// ---------------- kScan: 512 blocks (chunk x d-half), coalesced loads, BOTH tables ----------------
__global__ void kScan() {
    __shared__ float sLo[CS * HTS];       // 4224 B
    __shared__ float sHi[CS * HTS];       // 4224 B
    __shared__ float swlo[CS], swhi[CS];
    int tid = threadIdx.x;                // 256 (8 warps)
    int c = blockIdx.x >> 1, half = blockIdx.x & 1;
    int j0 = c * CS;
    int d0 = half * 32;
    if (tid < CS) {
        swlo[tid] = g_wlo[j0 + tid];
        swhi[tid] = g_whi[j0 + tid];
    }
    __syncthreads();
    int w = tid >> 5, lane = tid & 31;
#pragma unroll
    for (int it = 0; it < 4; it++) {
        int j = it * 8 + w;
        float hv = g_hs[(size_t)(j0 + j) * D + d0 + lane];   // coalesced, no indirection
        sLo[j * HTS + lane] = swlo[j] * hv;
        sHi[j * HTS + lane] = swhi[j] * hv;
    }
    if (half == 0 && tid < CS) {
        sLo[tid * HTS + 32] = swlo[tid];
        sHi[tid * HTS + 32] = swhi[tid];
    }
    __syncthreads();
    const unsigned F = 0xFFFFFFFFu;
    int ncols = (half == 0) ? 33 : 32;   // col 32 of half 0 = z column
    if (w < 4) {       // Lo forward scans
        for (int dd = w; dd < ncols; dd += 4) {
            float v = sLo[lane * HTS + dd];
#pragma unroll
            for (int o = 1; o < 32; o <<= 1) { float t = __shfl_up_sync(F, v, o); if (lane >= o) v += t; }
            sLo[lane * HTS + dd] = v;
            if (lane == 31) {
                if (dd < 32) g_ofLo[(d0 + dd) * NC + c] = v; else g_ofzLo[c] = v;
            }
        }
    } else {           // Hi backward scans
        for (int dd = w - 4; dd < ncols; dd += 4) {
            float v = sHi[lane * HTS + dd];
#pragma unroll
            for (int o = 1; o < 32; o <<= 1) { float t = __shfl_down_sync(F, v, o); if (lane + o < 32) v += t; }
            sHi[lane * HTS + dd] = v;
            if (lane == 0) {
                if (dd < 32) g_ofHi[(d0 + dd) * NC + c] = v; else g_ofzHi[c] = v;
            }
        }
    }
    __syncthreads();
#pragma unroll
    for (int it = 0; it < 4; it++) {
        int j = it * 8 + w;
        g_LoP[(size_t)(j0 + j + 1) * D + d0 + lane] = sLo[j * HTS + lane];
        g_HiS[(size_t)(j0 + j) * D + d0 + lane]     = sHi[j * HTS + lane];
    }
    if (half == 0 && tid < CS) {
        g_zLo[j0 + tid + 1] = sLo[tid * HTS + 32];
        g_zHi[j0 + tid]     = sHi[tid * HTS + 32];
    }
    if (c == 0) {
        if (tid < 32) g_LoP[d0 + tid] = 0.f;
        if (half == 0 && tid == 32) g_zLo[0] = 0.f;
    }
    if (c == NC - 1) {
        if (tid < 32) g_HiS[(size_t)NN * D + d0 + tid] = 0.f;
        if (half == 0 && tid == 32) g_zHi[NN] = 0.f;
    }
}

// ---------------- kS2: batched in-place scan of [d][c] chunk totals ----------------
__global__ void kS2() {
    int t = blockIdx.x * 4 + (threadIdx.x >> 5);
    int lane = threadIdx.x & 31;
    if (t >= 130) return;
    const unsigned F = 0xFFFFFFFFu;
    float* base;
    bool fwd;
    if (t < 64)        { base = g_ofLo + t * NC;        fwd = true;  }
    else if (t < 128)  { base = g_ofHi + (t - 64) * NC; fwd = false; }
    else if (t == 128) { base = g_ofzLo;                fwd = true;  }
    else               { base = g_ofzHi;                fwd = false; }
    float v[8], s[8];
#pragma unroll
    for (int m = 0; m < 8; m++) v[m] = base[m * 32 + lane];   // batched loads (MLP=8)
    if (fwd) {
#pragma unroll
        for (int m = 0; m < 8; m++) {
            float x = v[m];
#pragma unroll
            for (int o = 1; o < 32; o <<= 1) { float tt = __shfl_up_sync(F, x, o); if (lane >= o) x += tt; }
            s[m] = x;
        }
        float off = 0.f;
#pragma unroll
        for (int m = 0; m < 8; m++) {
            float tot = __shfl_sync(F, s[m], 31);
            base[m * 32 + lane] = off + s[m] - v[m];          // exclusive prefix
            off += tot;
        }
    } else {
#pragma unroll
        for (int m = 0; m < 8; m++) {
            float x = v[m];
#pragma unroll
            for (int o = 1; o < 32; o <<= 1) { float tt = __shfl_down_sync(F, x, o); if (lane + o < 32) x += tt; }
            s[m] = x;
        }
        float off = 0.f;
#pragma unroll
        for (int m = 7; m >= 0; m--) {
            float tot = __shfl_sync(F, s[m], 0);
            base[m * 32 + lane] = off + s[m] - v[m];          // exclusive suffix
            off += tot;
        }
    }
}

// ---------------- kOut: per-row combine + ELU ----------------
__global__ void kOut(float* __restrict__ out) {
    __shared__ float sf[256];             // f2s samples at stride 32
    int tid = threadIdx.x;                // 256
    sf[tid] = g_f2s[tid * 32];
    __syncthreads();
    int w = tid >> 5, lane = tid & 31;
    int i = blockIdx.x * 8 + w;
    float f1 = g_f1[i];
    float thr = -f1;
    const unsigned F = 0xFFFFFFFFu;
    int lo = 0, hi = 256;
#pragma unroll
    for (int it = 0; it < 8; it++) { int m = (lo + hi) >> 1; lo = (sf[m] <= thr) ? m + 1 : lo; hi = (sf[m] <= thr) ? hi : m; }
    int k;
    if (lo == 0) {
        __ballot_sync(F, false);
        k = 0;
    } else {
        int win = lo - 1;                 // f2s[win*32] <= thr; k in [win*32+1, win*32+32]
        int idx = win * 32 + 1 + lane;
        unsigned m = __ballot_sync(F, (idx < NN) ? (g_f2s[idx] <= thr) : false);
        k = win * 32 + 1 + __popc(m);
    }
    int ckLo = (k == 0) ? 0 : ((k - 1) >> 5);
    int ckHi = k >> 5;
    bool hasHi = (k < NN);
    float e1 = expf(f1), ea = expf(ALPHA * f1);
    float zLoV = g_zLo[k] + g_ofzLo[ckLo];
    float zHiV = hasHi ? (g_zHi[k] + g_ofzHi[ckHi]) : 0.f;
    float inv = 1.0f / (e1 * zHiV + ea * zLoV);
#pragma unroll
    for (int p = 0; p < 2; p++) {
        int d = lane + 32 * p;
        float lov = g_LoP[(size_t)k * D + d] + g_ofLo[d * NC + ckLo];
        float hiv = hasHi ? (g_HiS[(size_t)k * D + d] + g_ofHi[d * NC + ckHi]) : 0.f;
        float r = (e1 * hiv + ea * lov) * inv;
        out[i * D + d] = (r > 0.f) ? r : (expf(r) - 1.f);
    }
}

extern "C" void kernel_launch(void* const* d_in, const int* in_sizes, int n_in,
                              void* d_out, int out_size) {
    const float* x  = (const float*)d_in[0];
    const float* Wt = (const float*)d_in[1];
    const float* a1 = (const float*)d_in[2];
    const float* b1 = (const float*)d_in[3];
    const float* a2 = (const float*)d_in[4];
    const float* b2 = (const float*)d_in[5];
    float* out = (float*)d_out;

    k1<<<NN / 16, 256>>>(x, Wt, a1, b1, a2, b2);
    kRank<<<1024, 128>>>();
    kScan<<<NC * 2, 256>>>();
    kS2<<<33, 128>>>();
    kOut<<<NN / 8, 256>>>(out);
}

// round 15
// speedup vs baseline: 1.3779x; 1.3779x over previous
#include <cuda_runtime.h>

#define NN 8192
#define D 64
#define ALPHA 0.2f
#define CS 16          // scan chunk size (one width-16 warp-scan)
#define NC 512         // number of chunks (NN/CS)
#define TS2 34         // tile stride: (2*jj + dd) pattern hits all 32 banks

// ---------------- device scratch (no allocation allowed) ----------------
__device__ float g_h[NN * D];
__device__ float g_f1[NN];
__device__ float g_f2[NN];
__device__ unsigned g_key[NN];
__device__ unsigned g_rank[NN];        // low 20 bits: rank accum; bits 20+: arrival count
__device__ int   g_perm[NN];
__device__ float g_f2s[NN];
__device__ float g_wlo[NN];            // exp(alpha * f2), sorted order
__device__ float g_whi[NN];            // exp(f2), sorted order
__device__ float g_LoP[(NN + 1) * D];  // chunk-local fwd prefix of wlo*h
__device__ float g_HiS[(NN + 1) * D];  // chunk-local bwd suffix of whi*h
__device__ float g_zLo[NN + 1];
__device__ float g_zHi[NN + 1];
__device__ float g_ofLo[D * NC];       // [d][c] totals -> exclusive offsets (in place)
__device__ float g_ofHi[D * NC];       // [d][c]
__device__ float g_ofzLo[NC];
__device__ float g_ofzHi[NC];

// ---------------- k1: h = x@Wt (16 rows/block), f1/f2, keys, zero ranks ----------------
__global__ void k1(const float* __restrict__ x, const float* __restrict__ Wt,
                   const float* __restrict__ a1, const float* __restrict__ b1,
                   const float* __restrict__ a2, const float* __restrict__ b2) {
    __shared__ float sW[D * D];
    __shared__ float sx[16][D];
    __shared__ float sh[16][D];
    int tid = threadIdx.x;        // 256
    int row0 = blockIdx.x * 16;
    for (int i = tid; i < D * D; i += 256) sW[i] = Wt[i];
    for (int i = tid; i < 16 * D; i += 256) sx[i >> 6][i & 63] = x[row0 * D + i];
    __syncthreads();
    int o = tid & 63, rg = tid >> 6;
    float a0 = 0.f, a1c = 0.f, a2c = 0.f, a3 = 0.f;
#pragma unroll
    for (int i = 0; i < D; i++) {
        float w = sW[i * D + o];
        a0  += sx[rg * 4 + 0][i] * w;
        a1c += sx[rg * 4 + 1][i] * w;
        a2c += sx[rg * 4 + 2][i] * w;
        a3  += sx[rg * 4 + 3][i] * w;
    }
    g_h[(row0 + rg * 4 + 0) * D + o] = a0;
    g_h[(row0 + rg * 4 + 1) * D + o] = a1c;
    g_h[(row0 + rg * 4 + 2) * D + o] = a2c;
    g_h[(row0 + rg * 4 + 3) * D + o] = a3;
    sh[rg * 4 + 0][o] = a0;
    sh[rg * 4 + 1][o] = a1c;
    sh[rg * 4 + 2][o] = a2c;
    sh[rg * 4 + 3][o] = a3;
    __syncthreads();
    int w = tid >> 5, lane = tid & 31;
#pragma unroll
    for (int q = 0; q < 2; q++) {
        int r = w * 2 + q;
        float h0 = sh[r][lane], h1 = sh[r][lane + 32];
        float s1 = h0 * a1[lane] + h1 * a1[lane + 32];
        float s2 = h0 * a2[lane] + h1 * a2[lane + 32];
#pragma unroll
        for (int off = 16; off; off >>= 1) {
            s1 += __shfl_down_sync(0xFFFFFFFFu, s1, off);
            s2 += __shfl_down_sync(0xFFFFFFFFu, s2, off);
        }
        if (lane == 0) {
            int row = row0 + r;
            float f1v = s1 + b1[0], f2v = s2 + b2[0];
            g_f1[row] = f1v;
            g_f2[row] = f2v;
            unsigned u = __float_as_uint(f2v);
            g_key[row] = (u >> 31) ? ~u : (u | 0x80000000u);  // order-preserving
            g_rank[row] = 0u;
        }
    }
}

// ---------------- kRank: brute-force counting rank + FUSED scatter (round-11 proven) ----------------
// 1024 blocks = eb(64, element-chunk of 128) x cb(16, key-chunk of 512).
__global__ void kRank() {
    __shared__ unsigned sk[512];
    int tid = threadIdx.x;  // 128
    int eb = blockIdx.x >> 4, cb = blockIdx.x & 15;
    int i = eb * 128 + tid;
    unsigned ki = g_key[i];
#pragma unroll
    for (int m = 0; m < 4; m++) sk[tid + m * 128] = g_key[cb * 512 + tid + m * 128];
    __syncthreads();
    unsigned cnt = 0;
    int diag = eb >> 2;    // cb containing this eb's i-range
    if (cb == diag) {
        int j0 = cb * 512;
        for (int j = 0; j < 512; j++) {
            unsigned kj = sk[j];
            cnt += (kj < ki) || (kj == ki && (j0 + j) < i);
        }
    } else if (cb < diag) {   // all j < i: ties count
#pragma unroll 8
        for (int j = 0; j < 512; j++) cnt += (sk[j] <= ki);
    } else {                  // all j > i: ties don't count
#pragma unroll 8
        for (int j = 0; j < 512; j++) cnt += (sk[j] < ki);
    }
    unsigned old = atomicAdd(&g_rank[i], cnt + (1u << 20));
    if ((old >> 20) == 15u) {                 // final arrival performs scatter
        int r = (int)((old & 0xFFFFFu) + cnt);
        float f = g_f2[i];
        g_perm[r] = i;
        g_f2s[r] = f;
        g_wlo[r] = expf(ALPHA * f);
        g_whi[r] = expf(f);
    }
}

// ---------------- kScan: 1024 blocks (chunk x d-half), CS=16, width-16 scans ----------------
__global__ void kScan() {
    __shared__ float sLo[CS * TS2];       // 2176 B
    __shared__ float sHi[CS * TS2];       // 2176 B
    __shared__ int   sperm[CS];
    __shared__ float swlo[CS], swhi[CS];
    int tid = threadIdx.x;                // 256 (8 warps)
    int c = blockIdx.x >> 1, half = blockIdx.x & 1;
    int j0 = c * CS;
    int d0 = half * 32;
    if (tid < CS) {
        sperm[tid] = g_perm[j0 + tid];
        swlo[tid] = g_wlo[j0 + tid];
        swhi[tid] = g_whi[j0 + tid];
    }
    __syncthreads();
    int w = tid >> 5, lane = tid & 31;
#pragma unroll
    for (int it = 0; it < 2; it++) {
        int j = it * 8 + w;                               // 0..15
        float hv = g_h[(size_t)sperm[j] * D + d0 + lane];
        sLo[j * TS2 + lane] = swlo[j] * hv;
        sHi[j * TS2 + lane] = swhi[j] * hv;
    }
    if (half == 0 && tid < CS) {
        sLo[tid * TS2 + 32] = swlo[tid];
        sHi[tid * TS2 + 32] = swhi[tid];
    }
    __syncthreads();
    const unsigned F = 0xFFFFFFFFu;
    int ncols = (half == 0) ? 33 : 32;    // col 32 of half 0 = z column
    int sub = lane >> 4, jj = lane & 15;  // each warp scans 2 columns at once
    // warps 0-3: Lo forward; warps 4-7: Hi backward
    if (w < 4) {
#pragma unroll
        for (int r = 0; r < 5; r++) {     // dd = w*2+sub + 8*r covers 0..39
            int dd = w * 2 + sub + 8 * r;
            bool act = dd < ncols;
            float v = act ? sLo[jj * TS2 + dd] : 0.f;
#pragma unroll
            for (int o = 1; o < 16; o <<= 1) { float t = __shfl_up_sync(F, v, o, 16); if (jj >= o) v += t; }
            if (act) {
                sLo[jj * TS2 + dd] = v;
                if (jj == 15) {
                    if (dd < 32) g_ofLo[(d0 + dd) * NC + c] = v; else g_ofzLo[c] = v;
                }
            }
        }
    } else {
#pragma unroll
        for (int r = 0; r < 5; r++) {
            int dd = (w - 4) * 2 + sub + 8 * r;
            bool act = dd < ncols;
            float v = act ? sHi[jj * TS2 + dd] : 0.f;
#pragma unroll
            for (int o = 1; o < 16; o <<= 1) { float t = __shfl_down_sync(F, v, o, 16); if (jj + o < 16) v += t; }
            if (act) {
                sHi[jj * TS2 + dd] = v;
                if (jj == 0) {
                    if (dd < 32) g_ofHi[(d0 + dd) * NC + c] = v; else g_ofzHi[c] = v;
                }
            }
        }
    }
    __syncthreads();
#pragma unroll
    for (int it = 0; it < 2; it++) {
        int j = it * 8 + w;
        g_LoP[(size_t)(j0 + j + 1) * D + d0 + lane] = sLo[j * TS2 + lane];
        g_HiS[(size_t)(j0 + j) * D + d0 + lane]     = sHi[j * TS2 + lane];
    }
    if (half == 0 && tid < CS) {
        g_zLo[j0 + tid + 1] = sLo[tid * TS2 + 32];
        g_zHi[j0 + tid]     = sHi[tid * TS2 + 32];
    }
    if (c == 0) {
        if (tid < 32) g_LoP[d0 + tid] = 0.f;
        if (half == 0 && tid == 32) g_zLo[0] = 0.f;
    }
    if (c == NC - 1) {
        if (tid < 32) g_HiS[(size_t)NN * D + d0 + tid] = 0.f;
        if (half == 0 && tid == 32) g_zHi[NN] = 0.f;
    }
}

// ---------------- kS2: batched in-place scan of [d][c] chunk totals (16 segments) ----------------
__global__ void kS2() {
    int t = blockIdx.x * 4 + (threadIdx.x >> 5);
    int lane = threadIdx.x & 31;
    if (t >= 130) return;
    const unsigned F = 0xFFFFFFFFu;
    float* base;
    bool fwd;
    if (t < 64)        { base = g_ofLo + t * NC;        fwd = true;  }
    else if (t < 128)  { base = g_ofHi + (t - 64) * NC; fwd = false; }
    else if (t == 128) { base = g_ofzLo;                fwd = true;  }
    else               { base = g_ofzHi;                fwd = false; }
    float v[16], s[16];
#pragma unroll
    for (int m = 0; m < 16; m++) v[m] = base[m * 32 + lane];   // batched loads (MLP=16)
    if (fwd) {
#pragma unroll
        for (int m = 0; m < 16; m++) {
            float x = v[m];
#pragma unroll
            for (int o = 1; o < 32; o <<= 1) { float tt = __shfl_up_sync(F, x, o); if (lane >= o) x += tt; }
            s[m] = x;
        }
        float off = 0.f;
#pragma unroll
        for (int m = 0; m < 16; m++) {
            float tot = __shfl_sync(F, s[m], 31);
            base[m * 32 + lane] = off + s[m] - v[m];          // exclusive prefix
            off += tot;
        }
    } else {
#pragma unroll
        for (int m = 0; m < 16; m++) {
            float x = v[m];
#pragma unroll
            for (int o = 1; o < 32; o <<= 1) { float tt = __shfl_down_sync(F, x, o); if (lane + o < 32) x += tt; }
            s[m] = x;
        }
        float off = 0.f;
#pragma unroll
        for (int m = 15; m >= 0; m--) {
            float tot = __shfl_sync(F, s[m], 0);
            base[m * 32 + lane] = off + s[m] - v[m];          // exclusive suffix
            off += tot;
        }
    }
}

// ---------------- kOut: per-row combine + ELU ----------------
__global__ void kOut(float* __restrict__ out) {
    __shared__ float sf[256];             // f2s samples at stride 32
    int tid = threadIdx.x;                // 256
    sf[tid] = g_f2s[tid * 32];
    __syncthreads();
    int w = tid >> 5, lane = tid & 31;
    int i = blockIdx.x * 8 + w;
    float f1 = g_f1[i];
    float thr = -f1;
    const unsigned F = 0xFFFFFFFFu;
    int lo = 0, hi = 256;
#pragma unroll
    for (int it = 0; it < 8; it++) { int m = (lo + hi) >> 1; lo = (sf[m] <= thr) ? m + 1 : lo; hi = (sf[m] <= thr) ? hi : m; }
    int k;
    if (lo == 0) {
        __ballot_sync(F, false);
        k = 0;
    } else {
        int win = lo - 1;                 // f2s[win*32] <= thr; k in [win*32+1, win*32+32]
        int idx = win * 32 + 1 + lane;
        unsigned m = __ballot_sync(F, (idx < NN) ? (g_f2s[idx] <= thr) : false);
        k = win * 32 + 1 + __popc(m);
    }
    int ckLo = (k == 0) ? 0 : ((k - 1) >> 4);
    int ckHi = (k >> 4) < (NC - 1) ? (k >> 4) : (NC - 1);
    bool hasHi = (k < NN);
    float e1 = expf(f1), ea = expf(ALPHA * f1);
    float zLoV = g_zLo[k] + g_ofzLo[ckLo];
    float zHiV = hasHi ? (g_zHi[k] + g_ofzHi[ckHi]) : 0.f;
    float inv = 1.0f / (e1 * zHiV + ea * zLoV);
#pragma unroll
    for (int p = 0; p < 2; p++) {
        int d = lane + 32 * p;
        float lov = g_LoP[(size_t)k * D + d] + g_ofLo[d * NC + ckLo];
        float hiv = hasHi ? (g_HiS[(size_t)k * D + d] + g_ofHi[d * NC + ckHi]) : 0.f;
        float r = (e1 * hiv + ea * lov) * inv;
        out[i * D + d] = (r > 0.f) ? r : (expf(r) - 1.f);
    }
}

extern "C" void kernel_launch(void* const* d_in, const int* in_sizes, int n_in,
                              void* d_out, int out_size) {
    const float* x  = (const float*)d_in[0];
    const float* Wt = (const float*)d_in[1];
    const float* a1 = (const float*)d_in[2];
    const float* b1 = (const float*)d_in[3];
    const float* a2 = (const float*)d_in[4];
    const float* b2 = (const float*)d_in[5];
    float* out = (float*)d_out;

    k1<<<NN / 16, 256>>>(x, Wt, a1, b1, a2, b2);
    kRank<<<1024, 128>>>();
    kScan<<<NC * 2, 256>>>();
    kS2<<<33, 128>>>();
    kOut<<<NN / 8, 256>>>(out);
}